// round 14
// baseline (speedup 1.0000x reference)
#include <cuda_runtime.h>
#include <cuda_fp16.h>

#define N_NODES 200000
#define N_SUPER 20000
#define N_EDGES 640000
#define EMB 256
#define NBLK 196   // ceil(N_NODES / 1024) scan blocks

// ---------------- scratch (static device globals; no allocs) ----------------
__device__ __align__(16) __half   g_xh[(size_t)N_NODES * EMB];    // fp16 copy of x
__device__ __align__(16) __half   g_aggh[(size_t)N_NODES * EMB];  // fp16 agg rows
__device__ __align__(16) __half   g_projh[(size_t)N_SUPER * EMB]; // fp16 supernode x1 rows
__device__ __align__(16) __half   g_W2h[EMB * EMB];               // W2 in fp16
__device__ __align__(16) int      g_rowmap[N_NODES];
__device__ __align__(16) int      g_snode[N_SUPER];
__device__ __align__(16) int      g_cnt[N_NODES];
__device__ __align__(16) int      g_off[N_NODES + 1];
__device__ __align__(16) int      g_esrc[N_EDGES];                // node id, or N_NODES+slot
__device__ int g_bsum[NBLK];
__device__ int g_bpre[NBLK];
__device__ int g_is64;

// ---------------- helpers ----------------
__device__ __forceinline__ int load_idx(const void* p, int i) {
    if (g_is64) return (int)((const long long*)p)[i];
    return ((const int*)p)[i];
}

__device__ __forceinline__ unsigned f2tf(float f) {
    unsigned u;
    asm("cvt.rna.tf32.f32 %0, %1;" : "=r"(u) : "f"(f));
    return u;
}

__device__ __forceinline__ void mma_tf32(float* c, const unsigned* a, const unsigned* b) {
    asm volatile("mma.sync.aligned.m16n8k8.row.col.f32.tf32.tf32.f32 "
                 "{%0,%1,%2,%3}, {%4,%5,%6,%7}, {%8,%9}, {%0,%1,%2,%3};"
                 : "+f"(c[0]), "+f"(c[1]), "+f"(c[2]), "+f"(c[3])
                 : "r"(a[0]), "r"(a[1]), "r"(a[2]), "r"(a[3]), "r"(b[0]), "r"(b[1]));
}

__device__ __forceinline__ void mma_f16(float* c, const unsigned* a, const unsigned* b) {
    asm volatile("mma.sync.aligned.m16n8k16.row.col.f32.f16.f16.f32 "
                 "{%0,%1,%2,%3}, {%4,%5,%6,%7}, {%8,%9}, {%0,%1,%2,%3};"
                 : "+f"(c[0]), "+f"(c[1]), "+f"(c[2]), "+f"(c[3])
                 : "r"(a[0]), "r"(a[1]), "r"(a[2]), "r"(a[3]), "r"(b[0]), "r"(b[1]));
}

__device__ __forceinline__ const uint4* row_ptr_h(int idx) {
    const __half* p = (idx < N_NODES) ? (g_xh + (size_t)idx * EMB)
                                      : (g_projh + (size_t)(idx - N_NODES) * EMB);
    return (const uint4*)p;
}

__device__ __forceinline__ void acc_h8(float* a, uint4 r) {
    float2 f0 = __half22float2(*(__half2*)&r.x);
    float2 f1 = __half22float2(*(__half2*)&r.y);
    float2 f2 = __half22float2(*(__half2*)&r.z);
    float2 f3 = __half22float2(*(__half2*)&r.w);
    a[0] += f0.x; a[1] += f0.y; a[2] += f1.x; a[3] += f1.y;
    a[4] += f2.x; a[5] += f2.y; a[6] += f3.x; a[7] += f3.y;
}

// ---------------- init: detect + rowmap/cnt init + x->fp16 (fused) ----------------
__global__ void k_init(const int* __restrict__ ei_words, const float* __restrict__ x) {
    int i = blockIdx.x * blockDim.x + threadIdx.x;   // grid covers N*EMB/8 = 6.4M
    if (i == 0) {
        int all_zero = 1;
        for (int k = 0; k < 64; k++)
            if (ei_words[2 * k + 1] != 0) { all_zero = 0; break; }
        g_is64 = all_zero;
    }
    if (i < N_NODES) { g_rowmap[i] = -1; g_cnt[i] = 0; }
    if (i < N_SUPER) g_snode[i] = 0;
    if (i < N_NODES * (EMB / 8)) {
        float4 v0 = ((const float4*)x)[2 * i];
        float4 v1 = ((const float4*)x)[2 * i + 1];
        __half2 h0 = __floats2half2_rn(v0.x, v0.y);
        __half2 h1 = __floats2half2_rn(v0.z, v0.w);
        __half2 h2 = __floats2half2_rn(v1.x, v1.y);
        __half2 h3 = __floats2half2_rn(v1.z, v1.w);
        uint4 o;
        o.x = *(unsigned*)&h0; o.y = *(unsigned*)&h1;
        o.z = *(unsigned*)&h2; o.w = *(unsigned*)&h3;
        ((uint4*)g_xh)[i] = o;
    }
}

// rowmap/snode set + W2 fp16 convert (fused)
__global__ void k_prep2(const void* __restrict__ sidx, const float* __restrict__ W2) {
    int i = blockIdx.x * blockDim.x + threadIdx.x;   // grid covers 65536
    if (i < N_SUPER) {
        int v = load_idx(sidx, i);
        if (v >= 0 && v < N_NODES) { g_rowmap[v] = i; g_snode[i] = v; }
    }
    if (i < EMB * EMB) g_W2h[i] = __float2half_rn(W2[i]);
}

// ---------------- CSR build: histogram -> scan -> scatter ----------------
__global__ void k_hist(const void* __restrict__ ei) {
    int e = blockIdx.x * blockDim.x + threadIdx.x;
    if (e >= N_EDGES) return;
    int dst = load_idx(ei, e);
    if (dst >= 0 && dst < N_NODES) atomicAdd(&g_cnt[dst], 1);
}

__global__ void k_scan1() {
    __shared__ int s[256];
    int b = blockIdx.x, t = threadIdx.x;
    int base = b * 1024 + t * 4;
    int v[4], sum = 0;
#pragma unroll
    for (int i = 0; i < 4; i++) {
        v[i] = (base + i < N_NODES) ? g_cnt[base + i] : 0;
        sum += v[i];
    }
    s[t] = sum;
    __syncthreads();
#pragma unroll
    for (int off = 1; off < 256; off <<= 1) {
        int add = (t >= off) ? s[t - off] : 0;
        __syncthreads();
        s[t] += add;
        __syncthreads();
    }
    int run = (t ? s[t - 1] : 0);
#pragma unroll
    for (int i = 0; i < 4; i++) {
        if (base + i < N_NODES) g_off[base + i] = run;
        run += v[i];
    }
    if (t == 255) g_bsum[b] = s[255];
}

__global__ void k_scan2() {
    __shared__ int s[256];
    int t = threadIdx.x;
    s[t] = (t < NBLK) ? g_bsum[t] : 0;
    __syncthreads();
#pragma unroll
    for (int off = 1; off < 256; off <<= 1) {
        int add = (t >= off) ? s[t - off] : 0;
        __syncthreads();
        s[t] += add;
        __syncthreads();
    }
    if (t < NBLK) g_bpre[t] = (t ? s[t - 1] : 0);
    if (t == 0) g_off[N_NODES] = s[NBLK - 1];
}

__global__ void k_scan3() {
    int i = blockIdx.x * blockDim.x + threadIdx.x;
    if (i < N_NODES) {
        g_off[i] += g_bpre[i >> 10];
        g_cnt[i] = 0;
    }
}

__global__ void k_scatter(const void* __restrict__ ei) {
    int e = blockIdx.x * blockDim.x + threadIdx.x;
    if (e >= N_EDGES) return;
    int dst = load_idx(ei, e);
    int src = load_idx(ei, N_EDGES + e);
    if (dst < 0 || dst >= N_NODES || src < 0 || src >= N_NODES) return;
    int r = g_rowmap[src];
    int enc = (r >= 0) ? (N_NODES + r) : src;
    int pos = g_off[dst] + atomicAdd(&g_cnt[dst], 1);
    g_esrc[pos] = enc;
}

// ---------------- accumulate: fp16 gather, fp32 acc, fp16 store (proven R13) ------
__global__ void __launch_bounds__(256) k_accum() {
    int d = blockIdx.x * 8 + (threadIdx.x >> 5);
    if (d >= N_NODES) return;
    int lane = threadIdx.x & 31;
    int j   = g_off[d];
    int end = g_off[d + 1];
    float a[8];
#pragma unroll
    for (int t = 0; t < 8; t++) a[t] = 0.f;

    for (; j + 4 <= end; j += 4) {
        const uint4* p0 = row_ptr_h(g_esrc[j]);
        const uint4* p1 = row_ptr_h(g_esrc[j + 1]);
        const uint4* p2 = row_ptr_h(g_esrc[j + 2]);
        const uint4* p3 = row_ptr_h(g_esrc[j + 3]);
        uint4 r0 = p0[lane], r1 = p1[lane], r2 = p2[lane], r3 = p3[lane];
        acc_h8(a, r0); acc_h8(a, r1); acc_h8(a, r2); acc_h8(a, r3);
    }
    for (; j < end; j++)
        acc_h8(a, row_ptr_h(g_esrc[j])[lane]);

    __half2 h0 = __floats2half2_rn(a[0], a[1]);
    __half2 h1 = __floats2half2_rn(a[2], a[3]);
    __half2 h2 = __floats2half2_rn(a[4], a[5]);
    __half2 h3 = __floats2half2_rn(a[6], a[7]);
    uint4 o;
    o.x = *(unsigned*)&h0; o.y = *(unsigned*)&h1;
    o.z = *(unsigned*)&h2; o.w = *(unsigned*)&h3;
    ((uint4*)(g_aggh + (size_t)d * EMB))[lane] = o;
}

// ---------------- gemm1 (small, tf32): projh = fp16(x[snode] + snx @ W1^T + b1) ----
#define BM 64
#define BN 256
#define BK 32
#define PAD 36

__global__ void __launch_bounds__(256, 2)
k_gemm1(const float* __restrict__ A, const float* __restrict__ W,
        const float* __restrict__ bias, int M, const float* __restrict__ x)
{
    __shared__ unsigned As[BM * PAD];
    __shared__ unsigned Bs[BN * PAD];

    const int tid  = threadIdx.x;
    const int warp = tid >> 5, lane = tid & 31;
    const int wm   = warp >> 2, wn = warp & 3;
    const int gid  = lane >> 2, tg = lane & 3;
    const int row0 = blockIdx.x * BM;

    float c[2][8][4];
#pragma unroll
    for (int mt = 0; mt < 2; mt++)
#pragma unroll
        for (int nt = 0; nt < 8; nt++)
#pragma unroll
            for (int q = 0; q < 4; q++) c[mt][nt][q] = 0.f;

    for (int k0 = 0; k0 < EMB; k0 += BK) {
#pragma unroll
        for (int t = 0; t < 2; t++) {
            int f = tid + t * 256;
            int m = f >> 3, kq = f & 7;
            int row = row0 + m;
            float4 v = make_float4(0.f, 0.f, 0.f, 0.f);
            if (row < M) v = *(const float4*)(A + (size_t)row * EMB + k0 + kq * 4);
            unsigned* p = &As[m * PAD + kq * 4];
            p[0] = f2tf(v.x); p[1] = f2tf(v.y); p[2] = f2tf(v.z); p[3] = f2tf(v.w);
        }
#pragma unroll
        for (int t = 0; t < 8; t++) {
            int f = tid + t * 256;
            int n = f >> 3, kq = f & 7;
            float4 v = *(const float4*)(W + (size_t)n * EMB + k0 + kq * 4);
            unsigned* p = &Bs[n * PAD + kq * 4];
            p[0] = f2tf(v.x); p[1] = f2tf(v.y); p[2] = f2tf(v.z); p[3] = f2tf(v.w);
        }
        __syncthreads();

#pragma unroll
        for (int ks = 0; ks < BK; ks += 8) {
            unsigned a[2][4], b[8][2];
#pragma unroll
            for (int mt = 0; mt < 2; mt++) {
                int mb = wm * 32 + mt * 16 + gid;
                a[mt][0] = As[mb * PAD + ks + tg];
                a[mt][1] = As[(mb + 8) * PAD + ks + tg];
                a[mt][2] = As[mb * PAD + ks + tg + 4];
                a[mt][3] = As[(mb + 8) * PAD + ks + tg + 4];
            }
#pragma unroll
            for (int nt = 0; nt < 8; nt++) {
                int nb = wn * 64 + nt * 8 + gid;
                b[nt][0] = Bs[nb * PAD + ks + tg];
                b[nt][1] = Bs[nb * PAD + ks + tg + 4];
            }
#pragma unroll
            for (int mt = 0; mt < 2; mt++)
#pragma unroll
                for (int nt = 0; nt < 8; nt++)
                    mma_tf32(c[mt][nt], a[mt], b[nt]);
        }
        __syncthreads();
    }

#pragma unroll
    for (int mt = 0; mt < 2; mt++) {
#pragma unroll
        for (int half = 0; half < 2; half++) {
            int row = row0 + wm * 32 + mt * 16 + gid + half * 8;
            if (row >= M) continue;
            const float* addrow = x + (size_t)g_snode[row] * EMB;
#pragma unroll
            for (int nt = 0; nt < 8; nt++) {
                int col = wn * 64 + nt * 8 + 2 * tg;
                float v0 = c[mt][nt][half * 2 + 0] + bias[col];
                float v1 = c[mt][nt][half * 2 + 1] + bias[col + 1];
                float2 av = *(const float2*)(addrow + col);
                v0 += av.x; v1 += av.y;
                *(__half2*)(g_projh + (size_t)row * EMB + col) = __floats2half2_rn(v0, v1);
            }
        }
    }
}

// ---------------- gemm2 (final, fp16 mma): B fully smem-resident, A 2-stage -------
// BM=128 x BN=256, 512 threads (4x4 warps), BK=32 halves/stage.
#define G2_BM   128
#define AW      20                          // A words per row per stage (16 + 4 pad)
#define BWF     132                         // full-B words per row (128 + 4 pad)
#define G2_ASZ  (G2_BM * AW)                // 2560 words per A stage
#define G2_SMEM ((2 * G2_ASZ + 256 * BWF) * 4)   // 20480 + 135168 = 155,648 bytes

__device__ __forceinline__ void cpa16(unsigned daddr, const void* src, int sz) {
    asm volatile("cp.async.cg.shared.global [%0], [%1], 16, %2;"
                 :: "r"(daddr), "l"(src), "r"(sz));
}

__global__ void __launch_bounds__(512, 1)
k_gemm2(const float* __restrict__ bias, float* __restrict__ out)
{
    extern __shared__ unsigned sm2[];
    unsigned* Bs = sm2;                  // [256][BWF]
    unsigned* Asm = sm2 + 256 * BWF;     // 2 stages of [128][AW]

    const int tid  = threadIdx.x;
    const int warp = tid >> 5, lane = tid & 31;
    const int wm   = warp >> 2, wn = warp & 3;     // 4 x 4 warp grid
    const int gid  = lane >> 2, tg = lane & 3;
    const int row0 = blockIdx.x * G2_BM;

    // --- load full B (256 x 128 words = 8192 chunks; 16 per thread), group 0 ---
#pragma unroll
    for (int t = 0; t < 16; t++) {
        int ch = tid + t * 512;
        int n = ch >> 4, j = ch & 15;          // j = 16B chunk within row (8 chunks? no: 128 words = 32 chunks of 4)
        // 128 words per row = 32 uint4 chunks; 256*32 = 8192 chunks; ch>>5 = n, ch&31 = j
        n = ch >> 5; j = ch & 31;
        cpa16((unsigned)__cvta_generic_to_shared(&Bs[n * BWF + j * 4]),
              (const char*)g_W2h + ((size_t)n * EMB) * 2 + j * 16, 16);
    }
    asm volatile("cp.async.commit_group;" ::: "memory");

    // --- A stage loader: 128 rows x 32 halves = 512 chunks (1/thread) ---
    auto load_stage = [&](int k0, int buf) {   // k0 in halves
        unsigned* As = Asm + buf * G2_ASZ;
        int m = tid >> 2, j = tid & 3;
        int row = row0 + m;
        int ok = row < N_NODES;
        const char* src = (const char*)g_aggh +
                          ((size_t)(ok ? row : 0) * EMB + k0) * 2 + j * 16;
        cpa16((unsigned)__cvta_generic_to_shared(&As[m * AW + j * 4]),
              src, ok ? 16 : 0);
        asm volatile("cp.async.commit_group;" ::: "memory");
    };

    float c[2][8][4];
#pragma unroll
    for (int mt = 0; mt < 2; mt++)
#pragma unroll
        for (int nt = 0; nt < 8; nt++)
#pragma unroll
            for (int q = 0; q < 4; q++) c[mt][nt][q] = 0.f;

    load_stage(0, 0);

    for (int s = 0; s < 8; s++) {
        if (s < 7) {
            load_stage((s + 1) * 32, (s + 1) & 1);
            asm volatile("cp.async.wait_group 1;" ::: "memory");
        } else {
            asm volatile("cp.async.wait_group 0;" ::: "memory");
        }
        __syncthreads();

        const unsigned* As = Asm + (s & 1) * G2_ASZ;
        const int k0w = s * 16;   // word offset into B rows for this stage

#pragma unroll
        for (int kw = 0; kw < 16; kw += 8) {   // two K=16 mma steps per stage
            unsigned a[2][4], b[8][2];
#pragma unroll
            for (int mt = 0; mt < 2; mt++) {
                int mb = wm * 32 + mt * 16 + gid;
                a[mt][0] = As[mb * AW + kw + tg];
                a[mt][1] = As[(mb + 8) * AW + kw + tg];
                a[mt][2] = As[mb * AW + kw + tg + 4];
                a[mt][3] = As[(mb + 8) * AW + kw + tg + 4];
            }
#pragma unroll
            for (int nt = 0; nt < 8; nt++) {
                int nb = wn * 64 + nt * 8 + gid;
                b[nt][0] = Bs[nb * BWF + k0w + kw + tg];
                b[nt][1] = Bs[nb * BWF + k0w + kw + tg + 4];
            }
#pragma unroll
            for (int mt = 0; mt < 2; mt++)
#pragma unroll
                for (int nt = 0; nt < 8; nt++)
                    mma_f16(c[mt][nt], a[mt], b[nt]);
        }
        __syncthreads();
    }

    // epilogue: out = acc + b2*deg + x1[row] (x1 read as fp16)
#pragma unroll
    for (int mt = 0; mt < 2; mt++) {
#pragma unroll
        for (int half = 0; half < 2; half++) {
            int row = row0 + wm * 32 + mt * 16 + gid + half * 8;
            if (row >= N_NODES) continue;
            float dg = (float)(g_off[row + 1] - g_off[row]);
            int r = g_rowmap[row];
            const __half* addrow = (r >= 0) ? (g_projh + (size_t)r * EMB)
                                            : (g_xh + (size_t)row * EMB);
#pragma unroll
            for (int nt = 0; nt < 8; nt++) {
                int col = wn * 64 + nt * 8 + 2 * tg;
                float2 av = __half22float2(*(const __half2*)(addrow + col));
                float v0 = c[mt][nt][half * 2 + 0] + bias[col]     * dg + av.x;
                float v1 = c[mt][nt][half * 2 + 1] + bias[col + 1] * dg + av.y;
                *(float2*)(out + (size_t)row * EMB + col) = make_float2(v0, v1);
            }
        }
    }
}

// ---------------- launch ----------------
extern "C" void kernel_launch(void* const* d_in, const int* in_sizes, int n_in,
                              void* d_out, int out_size) {
    const float *x = nullptr, *snx = nullptr;
    const float *W1 = nullptr, *b1 = nullptr, *W2 = nullptr, *b2 = nullptr;
    const void  *ei = nullptr, *sidx = nullptr;

    for (int i = 0; i < n_in; i++) {
        int s = in_sizes[i];
        if      (s == N_NODES * EMB)  x    = (const float*)d_in[i];
        else if (s == N_SUPER * EMB)  snx  = (const float*)d_in[i];
        else if (s == 2 * N_EDGES)    ei   = d_in[i];
        else if (s == N_SUPER)        sidx = d_in[i];
        else if (s == N_NODES)        { /* graph_batch, unused */ }
        else if (s == EMB * EMB) { if (!W1) W1 = (const float*)d_in[i]; else W2 = (const float*)d_in[i]; }
        else if (s == EMB)       { if (!b1) b1 = (const float*)d_in[i]; else b2 = (const float*)d_in[i]; }
    }
    float* out = (float*)d_out;

    cudaFuncSetAttribute(k_gemm2, cudaFuncAttributeMaxDynamicSharedMemorySize, G2_SMEM);

    // init (detect + rowmap/cnt + x->fp16) ; prep2 (rowmap set + W2 cvt)
    k_init<<<(N_NODES * (EMB / 8) + 255) / 256, 256>>>((const int*)ei, x);
    k_prep2<<<(EMB * EMB + 255) / 256, 256>>>(sidx, W2);

    // CSR build
    k_hist<<<(N_EDGES + 255) / 256, 256>>>(ei);
    k_scan1<<<NBLK, 256>>>();
    k_scan2<<<1, 256>>>();
    k_scan3<<<(N_NODES + 255) / 256, 256>>>();
    k_scatter<<<(N_EDGES + 255) / 256, 256>>>(ei);

    // step 1: projh = fp16(x[sidx] + snx @ W1^T + b1)
    k_gemm1<<<(N_SUPER + BM - 1) / BM, 256>>>(snx, W1, b1, N_SUPER, x);

    // step 2a: agg rows (fp16 gather, fp32 accumulate, fp16 store)
    k_accum<<<(N_NODES + 7) / 8, 256>>>();

    // step 2b: out = x1 + agg @ W2^T + deg * b2   (fp16 mma, B smem-resident)
    k_gemm2<<<(N_NODES + G2_BM - 1) / G2_BM, 512, G2_SMEM>>>(b2, out);
}

// round 15
// speedup vs baseline: 1.0043x; 1.0043x over previous
#include <cuda_runtime.h>
#include <cuda_fp16.h>

#define N_NODES 200000
#define N_SUPER 20000
#define N_EDGES 640000
#define EMB 256
#define NBLK 196   // ceil(N_NODES / 1024) scan blocks

// ---------------- scratch (static device globals; no allocs) ----------------
__device__ __align__(16) __half   g_xh[(size_t)N_NODES * EMB];    // fp16 copy of x
__device__ __align__(16) __half   g_aggh[(size_t)N_NODES * EMB];  // fp16 agg rows
__device__ __align__(16) __half   g_projh[(size_t)N_SUPER * EMB]; // fp16 supernode x1 rows
__device__ __align__(16) __half   g_W2h[EMB * EMB];               // W2 in fp16
__device__ __align__(16) int      g_rowmap[N_NODES];              // 0 = none, else slot+1 (atomicMax)
__device__ __align__(16) int      g_snode[N_SUPER];
__device__ __align__(16) int      g_cnt[N_NODES];
__device__ __align__(16) int      g_off[N_NODES + 1];
__device__ __align__(16) int      g_esrc[N_EDGES];                // node id, or N_NODES+slot
__device__ int g_bsum[NBLK];
__device__ int g_bpre[NBLK];
__device__ int g_is64;

// ---------------- helpers ----------------
__device__ __forceinline__ int load_idx(const void* p, int i) {
    if (g_is64) return (int)((const long long*)p)[i];
    return ((const int*)p)[i];
}

__device__ __forceinline__ unsigned f2tf(float f) {
    unsigned u;
    asm("cvt.rna.tf32.f32 %0, %1;" : "=r"(u) : "f"(f));
    return u;
}

__device__ __forceinline__ void mma_tf32(float* c, const unsigned* a, const unsigned* b) {
    asm volatile("mma.sync.aligned.m16n8k8.row.col.f32.tf32.tf32.f32 "
                 "{%0,%1,%2,%3}, {%4,%5,%6,%7}, {%8,%9}, {%0,%1,%2,%3};"
                 : "+f"(c[0]), "+f"(c[1]), "+f"(c[2]), "+f"(c[3])
                 : "r"(a[0]), "r"(a[1]), "r"(a[2]), "r"(a[3]), "r"(b[0]), "r"(b[1]));
}

__device__ __forceinline__ void mma_f16(float* c, const unsigned* a, const unsigned* b) {
    asm volatile("mma.sync.aligned.m16n8k16.row.col.f32.f16.f16.f32 "
                 "{%0,%1,%2,%3}, {%4,%5,%6,%7}, {%8,%9}, {%0,%1,%2,%3};"
                 : "+f"(c[0]), "+f"(c[1]), "+f"(c[2]), "+f"(c[3])
                 : "r"(a[0]), "r"(a[1]), "r"(a[2]), "r"(a[3]), "r"(b[0]), "r"(b[1]));
}

__device__ __forceinline__ const uint4* row_ptr_h(int idx) {
    const __half* p = (idx < N_NODES) ? (g_xh + (size_t)idx * EMB)
                                      : (g_projh + (size_t)(idx - N_NODES) * EMB);
    return (const uint4*)p;
}

__device__ __forceinline__ void acc_h8(float* a, uint4 r) {
    float2 f0 = __half22float2(*(__half2*)&r.x);
    float2 f1 = __half22float2(*(__half2*)&r.y);
    float2 f2 = __half22float2(*(__half2*)&r.z);
    float2 f3 = __half22float2(*(__half2*)&r.w);
    a[0] += f0.x; a[1] += f0.y; a[2] += f1.x; a[3] += f1.y;
    a[4] += f2.x; a[5] += f2.y; a[6] += f3.x; a[7] += f3.y;
}

// ---------------- init: detect + cnt + rowmap/snode + W2h + x->fp16 (all fused) ----
__global__ void k_init(const int* __restrict__ ei_words, const float* __restrict__ x,
                       const void* __restrict__ sidx, const float* __restrict__ W2) {
    int i = blockIdx.x * blockDim.x + threadIdx.x;   // grid covers N*EMB/8 = 6.4M
    if (i == 0) {
        int all_zero = 1;
        for (int k = 0; k < 64; k++)
            if (ei_words[2 * k + 1] != 0) { all_zero = 0; break; }
        g_is64 = all_zero;
    }
    if (i < N_NODES) g_cnt[i] = 0;
    if (i < N_SUPER) {
        // local int64 detection (cannot rely on g_is64 within same launch)
        int is64 = (ei_words[1] == 0) & (ei_words[3] == 0) &
                   (ei_words[5] == 0) & (ei_words[7] == 0);
        int v = is64 ? (int)((const long long*)sidx)[i] : ((const int*)sidx)[i];
        if (v >= 0 && v < N_NODES) {
            atomicMax(&g_rowmap[v], i + 1);   // idempotent, replay-stable
            g_snode[i] = v;
        }
    }
    if (i < EMB * EMB) g_W2h[i] = __float2half_rn(W2[i]);
    if (i < N_NODES * (EMB / 8)) {
        float4 v0 = ((const float4*)x)[2 * i];
        float4 v1 = ((const float4*)x)[2 * i + 1];
        __half2 h0 = __floats2half2_rn(v0.x, v0.y);
        __half2 h1 = __floats2half2_rn(v0.z, v0.w);
        __half2 h2 = __floats2half2_rn(v1.x, v1.y);
        __half2 h3 = __floats2half2_rn(v1.z, v1.w);
        uint4 o;
        o.x = *(unsigned*)&h0; o.y = *(unsigned*)&h1;
        o.z = *(unsigned*)&h2; o.w = *(unsigned*)&h3;
        ((uint4*)g_xh)[i] = o;
    }
}

// ---------------- CSR build: histogram -> scan -> scatter ----------------
__global__ void k_hist(const void* __restrict__ ei) {
    int e = blockIdx.x * blockDim.x + threadIdx.x;
    if (e >= N_EDGES) return;
    int dst = load_idx(ei, e);
    if (dst >= 0 && dst < N_NODES) atomicAdd(&g_cnt[dst], 1);
}

__global__ void k_scan1() {
    __shared__ int s[256];
    int b = blockIdx.x, t = threadIdx.x;
    int base = b * 1024 + t * 4;
    int v[4], sum = 0;
#pragma unroll
    for (int i = 0; i < 4; i++) {
        v[i] = (base + i < N_NODES) ? g_cnt[base + i] : 0;
        sum += v[i];
    }
    s[t] = sum;
    __syncthreads();
#pragma unroll
    for (int off = 1; off < 256; off <<= 1) {
        int add = (t >= off) ? s[t - off] : 0;
        __syncthreads();
        s[t] += add;
        __syncthreads();
    }
    int run = (t ? s[t - 1] : 0);
#pragma unroll
    for (int i = 0; i < 4; i++) {
        if (base + i < N_NODES) g_off[base + i] = run;
        run += v[i];
    }
    if (t == 255) g_bsum[b] = s[255];
}

__global__ void k_scan2() {
    __shared__ int s[256];
    int t = threadIdx.x;
    s[t] = (t < NBLK) ? g_bsum[t] : 0;
    __syncthreads();
#pragma unroll
    for (int off = 1; off < 256; off <<= 1) {
        int add = (t >= off) ? s[t - off] : 0;
        __syncthreads();
        s[t] += add;
        __syncthreads();
    }
    if (t < NBLK) g_bpre[t] = (t ? s[t - 1] : 0);
    if (t == 0) g_off[N_NODES] = s[NBLK - 1];
}

__global__ void k_scan3() {
    int i = blockIdx.x * blockDim.x + threadIdx.x;
    if (i < N_NODES) {
        g_off[i] += g_bpre[i >> 10];
        g_cnt[i] = 0;
    }
}

__global__ void k_scatter(const void* __restrict__ ei) {
    int e = blockIdx.x * blockDim.x + threadIdx.x;
    if (e >= N_EDGES) return;
    int dst = load_idx(ei, e);
    int src = load_idx(ei, N_EDGES + e);
    if (dst < 0 || dst >= N_NODES || src < 0 || src >= N_NODES) return;
    int rm = g_rowmap[src];
    int enc = rm ? (N_NODES + rm - 1) : src;
    int pos = g_off[dst] + atomicAdd(&g_cnt[dst], 1);
    g_esrc[pos] = enc;
}

// ---------------- accumulate: fp16 gather, fp32 acc; MLP-batched tail -------------
__global__ void __launch_bounds__(256) k_accum() {
    int d = blockIdx.x * 8 + (threadIdx.x >> 5);
    if (d >= N_NODES) return;
    int lane = threadIdx.x & 31;
    int j   = g_off[d];
    int end = g_off[d + 1];
    float a[8];
#pragma unroll
    for (int t = 0; t < 8; t++) a[t] = 0.f;

    for (; j + 4 <= end; j += 4) {
        const uint4* p0 = row_ptr_h(g_esrc[j]);
        const uint4* p1 = row_ptr_h(g_esrc[j + 1]);
        const uint4* p2 = row_ptr_h(g_esrc[j + 2]);
        const uint4* p3 = row_ptr_h(g_esrc[j + 3]);
        uint4 r0 = p0[lane], r1 = p1[lane], r2 = p2[lane], r3 = p3[lane];
        acc_h8(a, r0); acc_h8(a, r1); acc_h8(a, r2); acc_h8(a, r3);
    }
    // tail (deg remainder 0..3): issue ALL loads before any accumulation
    {
        int rem = end - j;
        const uint4 *q0 = 0, *q1 = 0, *q2 = 0;
        if (rem > 0) q0 = row_ptr_h(g_esrc[j]);
        if (rem > 1) q1 = row_ptr_h(g_esrc[j + 1]);
        if (rem > 2) q2 = row_ptr_h(g_esrc[j + 2]);
        uint4 r0, r1, r2;
        if (q0) r0 = q0[lane];
        if (q1) r1 = q1[lane];
        if (q2) r2 = q2[lane];
        if (q0) acc_h8(a, r0);
        if (q1) acc_h8(a, r1);
        if (q2) acc_h8(a, r2);
    }

    __half2 h0 = __floats2half2_rn(a[0], a[1]);
    __half2 h1 = __floats2half2_rn(a[2], a[3]);
    __half2 h2 = __floats2half2_rn(a[4], a[5]);
    __half2 h3 = __floats2half2_rn(a[6], a[7]);
    uint4 o;
    o.x = *(unsigned*)&h0; o.y = *(unsigned*)&h1;
    o.z = *(unsigned*)&h2; o.w = *(unsigned*)&h3;
    ((uint4*)(g_aggh + (size_t)d * EMB))[lane] = o;
}

// ---------------- gemm1 (small, tf32): projh = fp16(x[snode] + snx @ W1^T + b1) ----
#define BM 64
#define BN 256
#define BK 32
#define PAD 36

__global__ void __launch_bounds__(256, 2)
k_gemm1(const float* __restrict__ A, const float* __restrict__ W,
        const float* __restrict__ bias, int M, const float* __restrict__ x)
{
    __shared__ unsigned As[BM * PAD];
    __shared__ unsigned Bs[BN * PAD];

    const int tid  = threadIdx.x;
    const int warp = tid >> 5, lane = tid & 31;
    const int wm   = warp >> 2, wn = warp & 3;
    const int gid  = lane >> 2, tg = lane & 3;
    const int row0 = blockIdx.x * BM;

    float c[2][8][4];
#pragma unroll
    for (int mt = 0; mt < 2; mt++)
#pragma unroll
        for (int nt = 0; nt < 8; nt++)
#pragma unroll
            for (int q = 0; q < 4; q++) c[mt][nt][q] = 0.f;

    for (int k0 = 0; k0 < EMB; k0 += BK) {
#pragma unroll
        for (int t = 0; t < 2; t++) {
            int f = tid + t * 256;
            int m = f >> 3, kq = f & 7;
            int row = row0 + m;
            float4 v = make_float4(0.f, 0.f, 0.f, 0.f);
            if (row < M) v = *(const float4*)(A + (size_t)row * EMB + k0 + kq * 4);
            unsigned* p = &As[m * PAD + kq * 4];
            p[0] = f2tf(v.x); p[1] = f2tf(v.y); p[2] = f2tf(v.z); p[3] = f2tf(v.w);
        }
#pragma unroll
        for (int t = 0; t < 8; t++) {
            int f = tid + t * 256;
            int n = f >> 3, kq = f & 7;
            float4 v = *(const float4*)(W + (size_t)n * EMB + k0 + kq * 4);
            unsigned* p = &Bs[n * PAD + kq * 4];
            p[0] = f2tf(v.x); p[1] = f2tf(v.y); p[2] = f2tf(v.z); p[3] = f2tf(v.w);
        }
        __syncthreads();

#pragma unroll
        for (int ks = 0; ks < BK; ks += 8) {
            unsigned a[2][4], b[8][2];
#pragma unroll
            for (int mt = 0; mt < 2; mt++) {
                int mb = wm * 32 + mt * 16 + gid;
                a[mt][0] = As[mb * PAD + ks + tg];
                a[mt][1] = As[(mb + 8) * PAD + ks + tg];
                a[mt][2] = As[mb * PAD + ks + tg + 4];
                a[mt][3] = As[(mb + 8) * PAD + ks + tg + 4];
            }
#pragma unroll
            for (int nt = 0; nt < 8; nt++) {
                int nb = wn * 64 + nt * 8 + gid;
                b[nt][0] = Bs[nb * PAD + ks + tg];
                b[nt][1] = Bs[nb * PAD + ks + tg + 4];
            }
#pragma unroll
            for (int mt = 0; mt < 2; mt++)
#pragma unroll
                for (int nt = 0; nt < 8; nt++)
                    mma_tf32(c[mt][nt], a[mt], b[nt]);
        }
        __syncthreads();
    }

#pragma unroll
    for (int mt = 0; mt < 2; mt++) {
#pragma unroll
        for (int half = 0; half < 2; half++) {
            int row = row0 + wm * 32 + mt * 16 + gid + half * 8;
            if (row >= M) continue;
            const float* addrow = x + (size_t)g_snode[row] * EMB;
#pragma unroll
            for (int nt = 0; nt < 8; nt++) {
                int col = wn * 64 + nt * 8 + 2 * tg;
                float v0 = c[mt][nt][half * 2 + 0] + bias[col];
                float v1 = c[mt][nt][half * 2 + 1] + bias[col + 1];
                float2 av = *(const float2*)(addrow + col);
                v0 += av.x; v1 += av.y;
                *(__half2*)(g_projh + (size_t)row * EMB + col) = __floats2half2_rn(v0, v1);
            }
        }
    }
}

// ---------------- gemm2 (final, fp16 mma): B resident, 3-stage A pipeline ---------
#define G2_BM   128
#define AW      20                          // A words per row per stage (16 + 4 pad)
#define BWF     132                         // full-B words per row (128 + 4 pad)
#define G2_ASZ  (G2_BM * AW)                // 2560 words per A stage
#define G2_NST  3
#define G2_SMEM ((G2_NST * G2_ASZ + 256 * BWF) * 4)   // 30720 + 135168 = 165,888 B

__device__ __forceinline__ void cpa16(unsigned daddr, const void* src, int sz) {
    asm volatile("cp.async.cg.shared.global [%0], [%1], 16, %2;"
                 :: "r"(daddr), "l"(src), "r"(sz));
}

__global__ void __launch_bounds__(512, 1)
k_gemm2(const float* __restrict__ bias, float* __restrict__ out)
{
    extern __shared__ unsigned sm2[];
    unsigned* Bs  = sm2;                 // [256][BWF]
    unsigned* Asm = sm2 + 256 * BWF;     // 3 stages of [128][AW]

    const int tid  = threadIdx.x;
    const int warp = tid >> 5, lane = tid & 31;
    const int wm   = warp >> 2, wn = warp & 3;     // 4 x 4 warp grid
    const int gid  = lane >> 2, tg = lane & 3;
    const int row0 = blockIdx.x * G2_BM;

    // --- full B load: 256 rows x 32 uint4 chunks = 8192; 16 per thread (group 0) ---
#pragma unroll
    for (int t = 0; t < 16; t++) {
        int ch = tid + t * 512;
        int n = ch >> 5, j = ch & 31;
        cpa16((unsigned)__cvta_generic_to_shared(&Bs[n * BWF + j * 4]),
              (const char*)g_W2h + ((size_t)n * EMB) * 2 + j * 16, 16);
    }
    asm volatile("cp.async.commit_group;" ::: "memory");

    // --- A stage loader: 128 rows x 32 halves = 512 chunks (1/thread) ---
    auto load_stage = [&](int s) {
        unsigned* As = Asm + (s % G2_NST) * G2_ASZ;
        int m = tid >> 2, j = tid & 3;
        int row = row0 + m;
        int ok = row < N_NODES;
        const char* src = (const char*)g_aggh +
                          ((size_t)(ok ? row : 0) * EMB + s * 32) * 2 + j * 16;
        cpa16((unsigned)__cvta_generic_to_shared(&As[m * AW + j * 4]),
              src, ok ? 16 : 0);
        asm volatile("cp.async.commit_group;" ::: "memory");
    };

    float c[2][8][4];
#pragma unroll
    for (int mt = 0; mt < 2; mt++)
#pragma unroll
        for (int nt = 0; nt < 8; nt++)
#pragma unroll
            for (int q = 0; q < 4; q++) c[mt][nt][q] = 0.f;

    load_stage(0);
    load_stage(1);

    for (int s = 0; s < 8; s++) {
        if (s < 6) {
            load_stage(s + 2);
            asm volatile("cp.async.wait_group 2;" ::: "memory");
        } else if (s == 6) {
            asm volatile("cp.async.wait_group 1;" ::: "memory");
        } else {
            asm volatile("cp.async.wait_group 0;" ::: "memory");
        }
        __syncthreads();

        const unsigned* As = Asm + (s % G2_NST) * G2_ASZ;
        const int k0w = s * 16;   // word offset into B rows for this stage

#pragma unroll
        for (int kw = 0; kw < 16; kw += 8) {   // two K=16 mma steps per stage
            unsigned a[2][4], b[8][2];
#pragma unroll
            for (int mt = 0; mt < 2; mt++) {
                int mb = wm * 32 + mt * 16 + gid;
                a[mt][0] = As[mb * AW + kw + tg];
                a[mt][1] = As[(mb + 8) * AW + kw + tg];
                a[mt][2] = As[mb * AW + kw + tg + 4];
                a[mt][3] = As[(mb + 8) * AW + kw + tg + 4];
            }
#pragma unroll
            for (int nt = 0; nt < 8; nt++) {
                int nb = wn * 64 + nt * 8 + gid;
                b[nt][0] = Bs[nb * BWF + k0w + kw + tg];
                b[nt][1] = Bs[nb * BWF + k0w + kw + tg + 4];
            }
#pragma unroll
            for (int mt = 0; mt < 2; mt++)
#pragma unroll
                for (int nt = 0; nt < 8; nt++)
                    mma_f16(c[mt][nt], a[mt], b[nt]);
        }
        __syncthreads();
    }

    // epilogue: out = acc + b2*deg + x1[row] (x1 read fp16)
#pragma unroll
    for (int mt = 0; mt < 2; mt++) {
#pragma unroll
        for (int half = 0; half < 2; half++) {
            int row = row0 + wm * 32 + mt * 16 + gid + half * 8;
            if (row >= N_NODES) continue;
            float dg = (float)(g_off[row + 1] - g_off[row]);
            int rm = g_rowmap[row];
            const __half* addrow = rm ? (g_projh + (size_t)(rm - 1) * EMB)
                                      : (g_xh + (size_t)row * EMB);
#pragma unroll
            for (int nt = 0; nt < 8; nt++) {
                int col = wn * 64 + nt * 8 + 2 * tg;
                float2 av = __half22float2(*(const __half2*)(addrow + col));
                float v0 = c[mt][nt][half * 2 + 0] + bias[col]     * dg + av.x;
                float v1 = c[mt][nt][half * 2 + 1] + bias[col + 1] * dg + av.y;
                *(float2*)(out + (size_t)row * EMB + col) = make_float2(v0, v1);
            }
        }
    }
}

// ---------------- launch ----------------
extern "C" void kernel_launch(void* const* d_in, const int* in_sizes, int n_in,
                              void* d_out, int out_size) {
    const float *x = nullptr, *snx = nullptr;
    const float *W1 = nullptr, *b1 = nullptr, *W2 = nullptr, *b2 = nullptr;
    const void  *ei = nullptr, *sidx = nullptr;

    for (int i = 0; i < n_in; i++) {
        int s = in_sizes[i];
        if      (s == N_NODES * EMB)  x    = (const float*)d_in[i];
        else if (s == N_SUPER * EMB)  snx  = (const float*)d_in[i];
        else if (s == 2 * N_EDGES)    ei   = d_in[i];
        else if (s == N_SUPER)        sidx = d_in[i];
        else if (s == N_NODES)        { /* graph_batch, unused */ }
        else if (s == EMB * EMB) { if (!W1) W1 = (const float*)d_in[i]; else W2 = (const float*)d_in[i]; }
        else if (s == EMB)       { if (!b1) b1 = (const float*)d_in[i]; else b2 = (const float*)d_in[i]; }
    }
    float* out = (float*)d_out;

    cudaFuncSetAttribute(k_gemm2, cudaFuncAttributeMaxDynamicSharedMemorySize, G2_SMEM);

    // fused init (detect + cnt + rowmap/snode + W2h + x->fp16)
    k_init<<<(N_NODES * (EMB / 8) + 255) / 256, 256>>>((const int*)ei, x, sidx, W2);

    // CSR build
    k_hist<<<(N_EDGES + 255) / 256, 256>>>(ei);
    k_scan1<<<NBLK, 256>>>();
    k_scan2<<<1, 256>>>();
    k_scan3<<<(N_NODES + 255) / 256, 256>>>();
    k_scatter<<<(N_EDGES + 255) / 256, 256>>>(ei);

    // step 1: projh = fp16(x[sidx] + snx @ W1^T + b1)
    k_gemm1<<<(N_SUPER + BM - 1) / BM, 256>>>(snx, W1, b1, N_SUPER, x);

    // step 2a: agg rows (fp16 gather, fp32 accumulate, fp16 store)
    k_accum<<<(N_NODES + 7) / 8, 256>>>();

    // step 2b: out = x1 + agg @ W2^T + deg * b2
    k_gemm2<<<(N_NODES + G2_BM - 1) / G2_BM, 512, G2_SMEM>>>(b2, out);
}